// round 8
// baseline (speedup 1.0000x reference)
#include <cuda_runtime.h>
#include <cuda_bf16.h>

#define NN 10000   // nodes
#define D  128     // d_model
#define KK 16      // d_state
#define S  5       // seq len
#define NS 4       // S-1
#define EE 320000  // edges
#define PP 80000   // edges per step
#define LN_EPS 1e-5f
#define M_CNT (NN * NS)          // 40000 counters
#define SCAN_BLKS 40
#define NPB 4                    // nodes per block (amortize weight loads)

// ---------------- device scratch (static, no allocation) ----------------
__device__ float g_Acont[D * KK];   // -exp(log_A)
__device__ int   g_cnt[M_CNT];
__device__ int   g_off[M_CNT + 1];
__device__ int   g_bsum[SCAN_BLKS];
__device__ int   g_bbase[SCAN_BLKS + 1];
__device__ int   g_cur[M_CNT];
__device__ int   g_csr[EE];         // packed: src | (etype<<16)

// ---------------- helpers ----------------
__device__ __forceinline__ float softplus_f(float v) {
    return (v > 20.f) ? v : log1pf(__expf(v));
}

// ---------------- prep: A_cont + zero counters ----------------
__global__ void prep_zero_kernel(const float* __restrict__ logA) {
    int i = blockIdx.x * blockDim.x + threadIdx.x;
    if (i < D * KK) g_Acont[i] = -expf(logA[i]);
    if (i < M_CNT) { g_cnt[i] = 0; g_cur[i] = 0; }
}

// ---------------- count edges per (dst, step) ----------------
__global__ void count_kernel(const int* __restrict__ perms,
                             const int* __restrict__ edge_index) {
    int i = blockIdx.x * blockDim.x + threadIdx.x;
    if (i >= NS * PP) return;
    int s = i / PP;
    int e = perms[i];
    int dst = edge_index[EE + e];
    atomicAdd(&g_cnt[dst * NS + s], 1);
}

// ---------------- hierarchical scan, phase A ----------------
__global__ __launch_bounds__(1024) void scanA_kernel() {
    __shared__ int wsum[32];
    int tid = threadIdx.x, lane = tid & 31, w = tid >> 5;
    int i = blockIdx.x * 1024 + tid;
    int v = (i < M_CNT) ? g_cnt[i] : 0;
    int incl = v;
    #pragma unroll
    for (int o = 1; o < 32; o <<= 1) {
        int t = __shfl_up_sync(0xffffffffu, incl, o);
        if (lane >= o) incl += t;
    }
    if (lane == 31) wsum[w] = incl;
    __syncthreads();
    if (w == 0) {
        int s0 = wsum[lane];
        int si = s0;
        #pragma unroll
        for (int o = 1; o < 32; o <<= 1) {
            int t = __shfl_up_sync(0xffffffffu, si, o);
            if (lane >= o) si += t;
        }
        wsum[lane] = si - s0;
    }
    __syncthreads();
    int excl = wsum[w] + incl - v;
    if (i <= M_CNT) g_off[i] = excl;
    if (tid == 1023) g_bsum[blockIdx.x] = wsum[31] + incl;
}

// ---------------- scan phase B ----------------
__global__ void scanB_kernel() {
    __shared__ int sh[2];
    int tid = threadIdx.x, lane = tid & 31, w = tid >> 5;   // 64 threads
    int v = (tid < SCAN_BLKS) ? g_bsum[tid] : 0;
    int incl = v;
    #pragma unroll
    for (int o = 1; o < 32; o <<= 1) {
        int t = __shfl_up_sync(0xffffffffu, incl, o);
        if (lane >= o) incl += t;
    }
    if (lane == 31) sh[w] = incl;
    __syncthreads();
    int base = (w == 1) ? sh[0] : 0;
    if (tid <= SCAN_BLKS) g_bbase[tid] = base + incl - v;
}

__device__ __forceinline__ int final_off(int i) {
    return g_off[i] + g_bbase[i >> 10];
}

// ---------------- fill CSR ----------------
__global__ void fill_kernel(const int* __restrict__ perms,
                            const int* __restrict__ edge_index,
                            const int* __restrict__ edge_type) {
    int i = blockIdx.x * blockDim.x + threadIdx.x;
    if (i >= NS * PP) return;
    int s = i / PP;
    int e = perms[i];
    int src = edge_index[e];
    int dst = edge_index[EE + e];
    int et  = edge_type[e];
    int idx = dst * NS + s;
    int pos = atomicAdd(&g_cur[idx], 1);
    g_csr[final_off(idx) + pos] = src | (et << 16);
}

// ---------------- mega kernel: NPB nodes per block ----------------
// Weight loads coalesced (row-major W[j*D+d]) and amortized over NPB nodes.
__global__ __launch_bounds__(128, 4) void mega_kernel(
    const float* __restrict__ x,
    const float* __restrict__ rel,
    const float* __restrict__ W_B,
    const float* __restrict__ W_C,
    const float* __restrict__ W_delta,
    const float* __restrict__ b_delta,
    const float* __restrict__ W_g,
    const float* __restrict__ b_g,
    const float* __restrict__ W_out,
    const float* __restrict__ b_out,
    const float* __restrict__ ln_g,
    const float* __restrict__ ln_b,
    float* __restrict__ out)
{
    int n0 = blockIdx.x * NPB;
    int d = threadIdx.x;                  // channel, 0..127
    int lane = d & 31, warp = d >> 5;

    __shared__ __align__(16) float tok[NPB][S][D];     // 10 KB
    __shared__ float BC[NPB][2][S][KK];                // 2.5 KB
    __shared__ float part[NPB][2][KK][4][S];           // 10 KB
    __shared__ __align__(16) float scn[NPB][D];        // 2 KB
    __shared__ float rs1[NPB][4], rs2[NPB][4];

    // ---- tokens: tok[m][0]=x[n], tok[m][1..4]=gather-mean over CSR ----
    float xv[NPB];
    #pragma unroll
    for (int m = 0; m < NPB; m++) {
        int n = n0 + m;
        xv[m] = x[n * D + d];
        tok[m][0][d] = xv[m];
        #pragma unroll
        for (int s = 0; s < NS; s++) {
            int idx = n * NS + s;
            int b = final_off(idx), e2 = final_off(idx + 1);
            float a0 = 0.f, a1 = 0.f, a2 = 0.f, a3 = 0.f;
            int t = b;
            for (; t + 4 <= e2; t += 4) {
                int p0 = g_csr[t], p1 = g_csr[t + 1];
                int p2 = g_csr[t + 2], p3 = g_csr[t + 3];
                a0 += x[(p0 & 0xFFFF) * D + d] + rel[(p0 >> 16) * D + d];
                a1 += x[(p1 & 0xFFFF) * D + d] + rel[(p1 >> 16) * D + d];
                a2 += x[(p2 & 0xFFFF) * D + d] + rel[(p2 >> 16) * D + d];
                a3 += x[(p3 & 0xFFFF) * D + d] + rel[(p3 >> 16) * D + d];
            }
            for (; t < e2; t++) {
                int pk = g_csr[t];
                a0 += x[(pk & 0xFFFF) * D + d] + rel[(pk >> 16) * D + d];
            }
            float acc = (a0 + a1) + (a2 + a3);
            int cnt = e2 - b;
            tok[m][1 + s][d] = acc / (float)(cnt > 1 ? cnt : 1);
        }
    }
    __syncthreads();

    // ---- delta GEMV (coalesced + amortized): dl[m][s] ----
    float dl[NPB][S];
    {
        float bd = b_delta[d];
        #pragma unroll
        for (int m = 0; m < NPB; m++)
            #pragma unroll
            for (int s = 0; s < S; s++) dl[m][s] = bd;
        #pragma unroll 4
        for (int j = 0; j < D; j += 4) {
            float w0 = W_delta[(j + 0) * D + d];
            float w1 = W_delta[(j + 1) * D + d];
            float w2 = W_delta[(j + 2) * D + d];
            float w3 = W_delta[(j + 3) * D + d];
            #pragma unroll
            for (int m = 0; m < NPB; m++) {
                #pragma unroll
                for (int s = 0; s < S; s++) {
                    float4 t4 = *(const float4*)&tok[m][s][j];
                    dl[m][s] += t4.x * w0 + t4.y * w1 + t4.z * w2 + t4.w * w3;
                }
            }
        }
        #pragma unroll
        for (int m = 0; m < NPB; m++)
            #pragma unroll
            for (int s = 0; s < S; s++) dl[m][s] = softplus_f(dl[m][s]);
    }

    // ---- B/C GEMVs: thread -> (mat, k, q); interleaved j = 4*i+q (no bank conflicts) ----
    {
        int mat = d >> 6;
        int k   = (d >> 2) & 15;
        int q   = d & 3;
        const float* W = mat ? W_C : W_B;
        #pragma unroll
        for (int m = 0; m < NPB; m++) {
            float acc[S] = {0.f, 0.f, 0.f, 0.f, 0.f};
            #pragma unroll 8
            for (int i = 0; i < 32; i++) {
                int j = 4 * i + q;
                float w = W[j * KK + k];
                #pragma unroll
                for (int s = 0; s < S; s++) acc[s] += tok[m][s][j] * w;
            }
            #pragma unroll
            for (int s = 0; s < S; s++) part[m][mat][k][q][s] = acc[s];
        }
    }
    __syncthreads();
    if (d < 2 * KK) {
        int mat = d >> 4, k = d & 15;
        #pragma unroll
        for (int m = 0; m < NPB; m++)
            #pragma unroll
            for (int s = 0; s < S; s++)
                BC[m][mat][s][k] = part[m][mat][k][0][s] + part[m][mat][k][1][s]
                                 + part[m][mat][k][2][s] + part[m][mat][k][3][s];
    }
    __syncthreads();

    // ---- bidirectional selective scan ----
    float A[KK];
    {
        const float4* ar = (const float4*)(g_Acont + d * KK);
        #pragma unroll
        for (int k4 = 0; k4 < 4; k4++) {
            float4 a4 = ar[k4];
            A[4 * k4 + 0] = a4.x; A[4 * k4 + 1] = a4.y;
            A[4 * k4 + 2] = a4.z; A[4 * k4 + 3] = a4.w;
        }
    }
    #pragma unroll
    for (int m = 0; m < NPB; m++) {
        float ysum = 0.f;
        {   // forward
            float st[KK];
            #pragma unroll
            for (int k = 0; k < KK; k++) st[k] = 0.f;
            #pragma unroll
            for (int s = 0; s < S; s++) {
                float dls = dl[m][s];
                float dx  = dls * tok[m][s][d];
                #pragma unroll
                for (int k = 0; k < KK; k++) {
                    float a = __expf(dls * A[k]);
                    st[k] = a * st[k] + dx * BC[m][0][s][k];
                    ysum += st[k] * BC[m][1][s][k];
                }
            }
        }
        {   // backward
            float st[KK];
            #pragma unroll
            for (int k = 0; k < KK; k++) st[k] = 0.f;
            #pragma unroll
            for (int s = S - 1; s >= 0; s--) {
                float dls = dl[m][s];
                float dx  = dls * tok[m][s][d];
                #pragma unroll
                for (int k = 0; k < KK; k++) {
                    float a = __expf(dls * A[k]);
                    st[k] = a * st[k] + dx * BC[m][0][s][k];
                    ysum += st[k] * BC[m][1][s][k];
                }
            }
        }
        scn[m][d] = ysum * (1.f / (float)S);
    }
    __syncthreads();

    // ---- gate & out GEMVs (coalesced + amortized) + residual ----
    float ga[NPB], oa[NPB];
    {
        float bg = b_g[d], bo = b_out[d];
        #pragma unroll
        for (int m = 0; m < NPB; m++) { ga[m] = bg; oa[m] = bo; }
        #pragma unroll 4
        for (int j = 0; j < D; j += 4) {
            float g0 = W_g[(j + 0) * D + d];
            float g1 = W_g[(j + 1) * D + d];
            float g2 = W_g[(j + 2) * D + d];
            float g3 = W_g[(j + 3) * D + d];
            float o0 = W_out[(j + 0) * D + d];
            float o1 = W_out[(j + 1) * D + d];
            float o2 = W_out[(j + 2) * D + d];
            float o3 = W_out[(j + 3) * D + d];
            #pragma unroll
            for (int m = 0; m < NPB; m++) {
                float4 x4 = *(const float4*)&tok[m][0][j];
                float4 s4 = *(const float4*)&scn[m][j];
                ga[m] += x4.x * g0 + x4.y * g1 + x4.z * g2 + x4.w * g3;
                oa[m] += s4.x * o0 + s4.y * o1 + s4.z * o2 + s4.w * o3;
            }
        }
    }

    // ---- residual + layernorm per node ----
    float res[NPB];
    #pragma unroll
    for (int m = 0; m < NPB; m++) {
        float gate = ga[m] / (1.f + __expf(-ga[m]));   // silu
        res[m] = xv[m] + gate * oa[m];
        float s1 = res[m], s2 = res[m] * res[m];
        #pragma unroll
        for (int o = 16; o > 0; o >>= 1) {
            s1 += __shfl_xor_sync(0xffffffffu, s1, o);
            s2 += __shfl_xor_sync(0xffffffffu, s2, o);
        }
        if (lane == 0) { rs1[m][warp] = s1; rs2[m][warp] = s2; }
    }
    __syncthreads();
    float lg = ln_g[d], lb = ln_b[d];
    #pragma unroll
    for (int m = 0; m < NPB; m++) {
        float t1 = rs1[m][0] + rs1[m][1] + rs1[m][2] + rs1[m][3];
        float t2 = rs2[m][0] + rs2[m][1] + rs2[m][2] + rs2[m][3];
        float mu  = t1 * (1.f / (float)D);
        float var = t2 * (1.f / (float)D) - mu * mu;
        float inv = rsqrtf(var + LN_EPS);
        out[(n0 + m) * D + d] = (res[m] - mu) * inv * lg + lb;
    }
}

// ---------------- launch ----------------
extern "C" void kernel_launch(void* const* d_in, const int* in_sizes, int n_in,
                              void* d_out, int out_size) {
    const float* x         = (const float*)d_in[0];
    const int*   edge_index= (const int*)  d_in[1];
    const int*   edge_type = (const int*)  d_in[2];
    const int*   perms     = (const int*)  d_in[3];
    const float* rel       = (const float*)d_in[4];
    const float* logA      = (const float*)d_in[5];
    const float* W_B       = (const float*)d_in[6];
    const float* W_C       = (const float*)d_in[7];
    const float* W_delta   = (const float*)d_in[8];
    const float* b_delta   = (const float*)d_in[9];
    const float* W_g       = (const float*)d_in[10];
    const float* b_g       = (const float*)d_in[11];
    const float* W_out     = (const float*)d_in[12];
    const float* b_out     = (const float*)d_in[13];
    const float* ln_g      = (const float*)d_in[14];
    const float* ln_b      = (const float*)d_in[15];
    float* out = (float*)d_out;

    prep_zero_kernel<<<(M_CNT + 255) / 256, 256>>>(logA);
    count_kernel<<<(NS * PP + 255) / 256, 256>>>(perms, edge_index);
    scanA_kernel<<<SCAN_BLKS, 1024>>>();
    scanB_kernel<<<1, 64>>>();
    fill_kernel<<<(NS * PP + 255) / 256, 256>>>(perms, edge_index, edge_type);
    mega_kernel<<<NN / NPB, 128>>>(x, rel, W_B, W_C, W_delta, b_delta,
                                   W_g, b_g, W_out, b_out, ln_g, ln_b, out);
}

// round 11
// speedup vs baseline: 2.1195x; 2.1195x over previous
#include <cuda_runtime.h>
#include <cuda_bf16.h>

#define NN 10000   // nodes
#define D  128     // d_model
#define KK 16      // d_state
#define S  5       // seq len
#define NS 4       // S-1
#define EE 320000  // edges
#define PP 80000   // edges per step
#define LN_EPS 1e-5f
#define M_CNT (NN * NS)          // 40000 counters
#define SCAN_BLKS 40
#define NPB 4                    // nodes per block in mamba_kernel

// ---------------- device scratch (static, no allocation) ----------------
__device__ float g_Acont[D * KK];   // -exp(log_A)
__device__ int   g_cnt[M_CNT];
__device__ int   g_off[M_CNT + 1];
__device__ int   g_bsum[SCAN_BLKS];
__device__ int   g_bbase[SCAN_BLKS + 1];
__device__ int   g_cur[M_CNT];
__device__ int   g_csr[EE];         // packed: src | (etype<<16)
__device__ float g_tok[NN * S * D]; // tokens [n][s][d]  (25.6 MB)

// ---------------- helpers ----------------
__device__ __forceinline__ float softplus_f(float v) {
    return (v > 20.f) ? v : log1pf(__expf(v));
}

// ---------------- prep: A_cont + zero counters ----------------
__global__ void prep_zero_kernel(const float* __restrict__ logA) {
    int i = blockIdx.x * blockDim.x + threadIdx.x;
    if (i < D * KK) g_Acont[i] = -expf(logA[i]);
    if (i < M_CNT) { g_cnt[i] = 0; g_cur[i] = 0; }
}

// ---------------- count edges per (dst, step) ----------------
__global__ void count_kernel(const int* __restrict__ perms,
                             const int* __restrict__ edge_index) {
    int i = blockIdx.x * blockDim.x + threadIdx.x;
    if (i >= NS * PP) return;
    int s = i / PP;
    int e = perms[i];
    int dst = edge_index[EE + e];
    atomicAdd(&g_cnt[dst * NS + s], 1);
}

// ---------------- hierarchical scan, phase A ----------------
__global__ __launch_bounds__(1024) void scanA_kernel() {
    __shared__ int wsum[32];
    int tid = threadIdx.x, lane = tid & 31, w = tid >> 5;
    int i = blockIdx.x * 1024 + tid;
    int v = (i < M_CNT) ? g_cnt[i] : 0;
    int incl = v;
    #pragma unroll
    for (int o = 1; o < 32; o <<= 1) {
        int t = __shfl_up_sync(0xffffffffu, incl, o);
        if (lane >= o) incl += t;
    }
    if (lane == 31) wsum[w] = incl;
    __syncthreads();
    if (w == 0) {
        int s0 = wsum[lane];
        int si = s0;
        #pragma unroll
        for (int o = 1; o < 32; o <<= 1) {
            int t = __shfl_up_sync(0xffffffffu, si, o);
            if (lane >= o) si += t;
        }
        wsum[lane] = si - s0;
    }
    __syncthreads();
    int excl = wsum[w] + incl - v;
    if (i <= M_CNT) g_off[i] = excl;
    if (tid == 1023) g_bsum[blockIdx.x] = wsum[31] + incl;
}

// ---------------- scan phase B ----------------
__global__ void scanB_kernel() {
    __shared__ int sh[2];
    int tid = threadIdx.x, lane = tid & 31, w = tid >> 5;   // 64 threads
    int v = (tid < SCAN_BLKS) ? g_bsum[tid] : 0;
    int incl = v;
    #pragma unroll
    for (int o = 1; o < 32; o <<= 1) {
        int t = __shfl_up_sync(0xffffffffu, incl, o);
        if (lane >= o) incl += t;
    }
    if (lane == 31) sh[w] = incl;
    __syncthreads();
    int base = (w == 1) ? sh[0] : 0;
    if (tid <= SCAN_BLKS) g_bbase[tid] = base + incl - v;
}

__device__ __forceinline__ int final_off(int i) {
    return g_off[i] + g_bbase[i >> 10];
}

// ---------------- fill CSR ----------------
__global__ void fill_kernel(const int* __restrict__ perms,
                            const int* __restrict__ edge_index,
                            const int* __restrict__ edge_type) {
    int i = blockIdx.x * blockDim.x + threadIdx.x;
    if (i >= NS * PP) return;
    int s = i / PP;
    int e = perms[i];
    int src = edge_index[e];
    int dst = edge_index[EE + e];
    int et  = edge_type[e];
    int idx = dst * NS + s;
    int pos = atomicAdd(&g_cur[idx], 1);
    g_csr[final_off(idx) + pos] = src | (et << 16);
}

// ---------------- tokenize kernel: one block per node (high occupancy) ----------------
__global__ __launch_bounds__(128) void tok_kernel(
    const float* __restrict__ x,
    const float* __restrict__ rel)
{
    int n = blockIdx.x;
    int d = threadIdx.x;
    float* trow = g_tok + n * (S * D);
    trow[d] = x[n * D + d];                       // token 0 = x[n]
    #pragma unroll
    for (int s = 0; s < NS; s++) {
        int idx = n * NS + s;
        int b = final_off(idx), e2 = final_off(idx + 1);
        float a0 = 0.f, a1 = 0.f, a2 = 0.f, a3 = 0.f;
        int t = b;
        for (; t + 4 <= e2; t += 4) {
            int p0 = g_csr[t], p1 = g_csr[t + 1];
            int p2 = g_csr[t + 2], p3 = g_csr[t + 3];
            a0 += x[(p0 & 0xFFFF) * D + d] + rel[(p0 >> 16) * D + d];
            a1 += x[(p1 & 0xFFFF) * D + d] + rel[(p1 >> 16) * D + d];
            a2 += x[(p2 & 0xFFFF) * D + d] + rel[(p2 >> 16) * D + d];
            a3 += x[(p3 & 0xFFFF) * D + d] + rel[(p3 >> 16) * D + d];
        }
        for (; t < e2; t++) {
            int pk = g_csr[t];
            a0 += x[(pk & 0xFFFF) * D + d] + rel[(pk >> 16) * D + d];
        }
        float acc = (a0 + a1) + (a2 + a3);
        int cnt = e2 - b;
        trow[(1 + s) * D + d] = acc / (float)(cnt > 1 ? cnt : 1);
    }
}

// ---------------- mamba kernel: NPB nodes per block, no gather ----------------
__global__ __launch_bounds__(128) void mamba_kernel(
    const float* __restrict__ W_B,
    const float* __restrict__ W_C,
    const float* __restrict__ W_delta,
    const float* __restrict__ b_delta,
    const float* __restrict__ W_g,
    const float* __restrict__ b_g,
    const float* __restrict__ W_out,
    const float* __restrict__ b_out,
    const float* __restrict__ ln_g,
    const float* __restrict__ ln_b,
    float* __restrict__ out)
{
    int n0 = blockIdx.x * NPB;
    int d = threadIdx.x;                  // channel, 0..127
    int lane = d & 31, warp = d >> 5;

    __shared__ __align__(16) float tok[NPB][S][D];     // 10 KB
    __shared__ float BC[NPB][2][S][KK];                // 2.5 KB
    __shared__ float part[NPB][2][KK][4][S];           // 10 KB
    __shared__ __align__(16) float scn[NPB][D];        // 2 KB
    __shared__ float rs1[NPB][4], rs2[NPB][4];

    // ---- stream tokens from gmem (coalesced float4) ----
    {
        const float4* src = (const float4*)(g_tok + n0 * (S * D));
        float4* dst = (float4*)&tok[0][0][0];
        #pragma unroll
        for (int i = d; i < NPB * S * D / 4; i += 128) dst[i] = src[i];
    }
    __syncthreads();

    float xv[NPB];
    #pragma unroll
    for (int m = 0; m < NPB; m++) xv[m] = tok[m][0][d];

    // ---- delta GEMV (coalesced + amortized): dl[m][s] ----
    float dl[NPB][S];
    {
        float bd = b_delta[d];
        #pragma unroll
        for (int m = 0; m < NPB; m++)
            #pragma unroll
            for (int s = 0; s < S; s++) dl[m][s] = bd;
        #pragma unroll 4
        for (int j = 0; j < D; j += 4) {
            float w0 = W_delta[(j + 0) * D + d];
            float w1 = W_delta[(j + 1) * D + d];
            float w2 = W_delta[(j + 2) * D + d];
            float w3 = W_delta[(j + 3) * D + d];
            #pragma unroll
            for (int m = 0; m < NPB; m++) {
                #pragma unroll
                for (int s = 0; s < S; s++) {
                    float4 t4 = *(const float4*)&tok[m][s][j];
                    dl[m][s] += t4.x * w0 + t4.y * w1 + t4.z * w2 + t4.w * w3;
                }
            }
        }
        #pragma unroll
        for (int m = 0; m < NPB; m++)
            #pragma unroll
            for (int s = 0; s < S; s++) dl[m][s] = softplus_f(dl[m][s]);
    }

    // ---- B/C GEMVs: thread -> (mat, k, q); interleaved j = 4*i+q ----
    {
        int mat = d >> 6;
        int k   = (d >> 2) & 15;
        int q   = d & 3;
        const float* W = mat ? W_C : W_B;
        #pragma unroll
        for (int m = 0; m < NPB; m++) {
            float acc[S] = {0.f, 0.f, 0.f, 0.f, 0.f};
            #pragma unroll 8
            for (int i = 0; i < 32; i++) {
                int j = 4 * i + q;
                float w = W[j * KK + k];
                #pragma unroll
                for (int s = 0; s < S; s++) acc[s] += tok[m][s][j] * w;
            }
            #pragma unroll
            for (int s = 0; s < S; s++) part[m][mat][k][q][s] = acc[s];
        }
    }
    __syncthreads();
    if (d < 2 * KK) {
        int mat = d >> 4, k = d & 15;
        #pragma unroll
        for (int m = 0; m < NPB; m++)
            #pragma unroll
            for (int s = 0; s < S; s++)
                BC[m][mat][s][k] = part[m][mat][k][0][s] + part[m][mat][k][1][s]
                                 + part[m][mat][k][2][s] + part[m][mat][k][3][s];
    }
    __syncthreads();

    // ---- bidirectional selective scan ----
    float A[KK];
    {
        const float4* ar = (const float4*)(g_Acont + d * KK);
        #pragma unroll
        for (int k4 = 0; k4 < 4; k4++) {
            float4 a4 = ar[k4];
            A[4 * k4 + 0] = a4.x; A[4 * k4 + 1] = a4.y;
            A[4 * k4 + 2] = a4.z; A[4 * k4 + 3] = a4.w;
        }
    }
    #pragma unroll
    for (int m = 0; m < NPB; m++) {
        float ysum = 0.f;
        {   // forward
            float st[KK];
            #pragma unroll
            for (int k = 0; k < KK; k++) st[k] = 0.f;
            #pragma unroll
            for (int s = 0; s < S; s++) {
                float dls = dl[m][s];
                float dx  = dls * tok[m][s][d];
                #pragma unroll
                for (int k = 0; k < KK; k++) {
                    float a = __expf(dls * A[k]);
                    st[k] = a * st[k] + dx * BC[m][0][s][k];
                    ysum += st[k] * BC[m][1][s][k];
                }
            }
        }
        {   // backward
            float st[KK];
            #pragma unroll
            for (int k = 0; k < KK; k++) st[k] = 0.f;
            #pragma unroll
            for (int s = S - 1; s >= 0; s--) {
                float dls = dl[m][s];
                float dx  = dls * tok[m][s][d];
                #pragma unroll
                for (int k = 0; k < KK; k++) {
                    float a = __expf(dls * A[k]);
                    st[k] = a * st[k] + dx * BC[m][0][s][k];
                    ysum += st[k] * BC[m][1][s][k];
                }
            }
        }
        scn[m][d] = ysum * (1.f / (float)S);
    }
    __syncthreads();

    // ---- gate & out GEMVs (coalesced + amortized) ----
    float ga[NPB], oa[NPB];
    {
        float bg = b_g[d], bo = b_out[d];
        #pragma unroll
        for (int m = 0; m < NPB; m++) { ga[m] = bg; oa[m] = bo; }
        #pragma unroll 4
        for (int j = 0; j < D; j += 4) {
            float g0 = W_g[(j + 0) * D + d];
            float g1 = W_g[(j + 1) * D + d];
            float g2 = W_g[(j + 2) * D + d];
            float g3 = W_g[(j + 3) * D + d];
            float o0 = W_out[(j + 0) * D + d];
            float o1 = W_out[(j + 1) * D + d];
            float o2 = W_out[(j + 2) * D + d];
            float o3 = W_out[(j + 3) * D + d];
            #pragma unroll
            for (int m = 0; m < NPB; m++) {
                float4 x4 = *(const float4*)&tok[m][0][j];
                float4 s4 = *(const float4*)&scn[m][j];
                ga[m] += x4.x * g0 + x4.y * g1 + x4.z * g2 + x4.w * g3;
                oa[m] += s4.x * o0 + s4.y * o1 + s4.z * o2 + s4.w * o3;
            }
        }
    }

    // ---- residual + layernorm per node ----
    float res[NPB];
    #pragma unroll
    for (int m = 0; m < NPB; m++) {
        float gate = ga[m] / (1.f + __expf(-ga[m]));   // silu
        res[m] = xv[m] + gate * oa[m];
        float s1 = res[m], s2 = res[m] * res[m];
        #pragma unroll
        for (int o = 16; o > 0; o >>= 1) {
            s1 += __shfl_xor_sync(0xffffffffu, s1, o);
            s2 += __shfl_xor_sync(0xffffffffu, s2, o);
        }
        if (lane == 0) { rs1[m][warp] = s1; rs2[m][warp] = s2; }
    }
    __syncthreads();
    float lg = ln_g[d], lb = ln_b[d];
    #pragma unroll
    for (int m = 0; m < NPB; m++) {
        float t1 = rs1[m][0] + rs1[m][1] + rs1[m][2] + rs1[m][3];
        float t2 = rs2[m][0] + rs2[m][1] + rs2[m][2] + rs2[m][3];
        float mu  = t1 * (1.f / (float)D);
        float var = t2 * (1.f / (float)D) - mu * mu;
        float inv = rsqrtf(var + LN_EPS);
        out[(n0 + m) * D + d] = (res[m] - mu) * inv * lg + lb;
    }
}

// ---------------- launch ----------------
extern "C" void kernel_launch(void* const* d_in, const int* in_sizes, int n_in,
                              void* d_out, int out_size) {
    const float* x         = (const float*)d_in[0];
    const int*   edge_index= (const int*)  d_in[1];
    const int*   edge_type = (const int*)  d_in[2];
    const int*   perms     = (const int*)  d_in[3];
    const float* rel       = (const float*)d_in[4];
    const float* logA      = (const float*)d_in[5];
    const float* W_B       = (const float*)d_in[6];
    const float* W_C       = (const float*)d_in[7];
    const float* W_delta   = (const float*)d_in[8];
    const float* b_delta   = (const float*)d_in[9];
    const float* W_g       = (const float*)d_in[10];
    const float* b_g       = (const float*)d_in[11];
    const float* W_out     = (const float*)d_in[12];
    const float* b_out     = (const float*)d_in[13];
    const float* ln_g      = (const float*)d_in[14];
    const float* ln_b      = (const float*)d_in[15];
    float* out = (float*)d_out;

    prep_zero_kernel<<<(M_CNT + 255) / 256, 256>>>(logA);
    count_kernel<<<(NS * PP + 255) / 256, 256>>>(perms, edge_index);
    scanA_kernel<<<SCAN_BLKS, 1024>>>();
    scanB_kernel<<<1, 64>>>();
    fill_kernel<<<(NS * PP + 255) / 256, 256>>>(perms, edge_index, edge_type);
    tok_kernel<<<NN, 128>>>(x, rel);
    mamba_kernel<<<NN / NPB, 128>>>(W_B, W_C, W_delta, b_delta,
                                    W_g, b_g, W_out, b_out, ln_g, ln_b, out);
}

// round 13
// speedup vs baseline: 2.4378x; 1.1502x over previous
#include <cuda_runtime.h>
#include <cuda_bf16.h>

#define NN 10000   // nodes
#define D  128     // d_model
#define KK 16      // d_state
#define S  5       // seq len
#define NS 4       // S-1
#define EE 320000  // edges
#define PP 80000   // edges per step
#define LN_EPS 1e-5f
#define M_CNT (NN * NS)          // 40000 counters
#define SCAN_BLKS 40
#define NPB 4                    // nodes per block in mamba_kernel

typedef unsigned long long u64;

// ---------------- f32x2 packed math (sm_103a FFMA2 path) ----------------
#define PACK2(out, lo, hi)  asm("mov.b64 %0, {%1, %2};" : "=l"(out) : "f"(lo), "f"(hi))
#define UNPACK2(lo, hi, in) asm("mov.b64 {%0, %1}, %2;" : "=f"(lo), "=f"(hi) : "l"(in))
#define FMA2(d_, a_, b_, c_) asm("fma.rn.f32x2 %0, %1, %2, %3;" : "=l"(d_) : "l"(a_), "l"(b_), "l"(c_))
#define MUL2(d_, a_, b_)     asm("mul.rn.f32x2 %0, %1, %2;"     : "=l"(d_) : "l"(a_), "l"(b_))
__device__ __forceinline__ float ex2f(float x) {
    float r; asm("ex2.approx.ftz.f32 %0, %1;" : "=f"(r) : "f"(x)); return r;
}

// ---------------- device scratch (static, no allocation) ----------------
__device__ float g_Acont[D * KK];   // -exp(log_A)
__device__ int   g_cnt[M_CNT];
__device__ int   g_off[M_CNT + 1];
__device__ int   g_bsum[SCAN_BLKS];
__device__ int   g_bbase[SCAN_BLKS + 1];
__device__ int   g_cur[M_CNT];
__device__ int   g_scan_done;
__device__ int   g_csr[EE];         // packed: src | (etype<<16)
__device__ float g_tok[NN * S * D]; // tokens [n][s][d]  (25.6 MB)

// ---------------- helpers ----------------
__device__ __forceinline__ float softplus_f(float v) {
    return (v > 20.f) ? v : log1pf(__expf(v));
}

// ---------------- prep: A_cont + zero counters ----------------
__global__ void prep_zero_kernel(const float* __restrict__ logA) {
    int i = blockIdx.x * blockDim.x + threadIdx.x;
    if (i < D * KK) g_Acont[i] = -expf(logA[i]);
    if (i < M_CNT) { g_cnt[i] = 0; g_cur[i] = 0; }
    if (i == 0) g_scan_done = 0;
}

// ---------------- count edges per (dst, step) ----------------
__global__ void count_kernel(const int* __restrict__ perms,
                             const int* __restrict__ edge_index) {
    int i = blockIdx.x * blockDim.x + threadIdx.x;
    if (i >= NS * PP) return;
    int s = i / PP;
    int e = perms[i];
    int dst = edge_index[EE + e];
    atomicAdd(&g_cnt[dst * NS + s], 1);
}

// ---------------- scan (fused hierarchical: per-block + last-block top scan) ----------------
__global__ __launch_bounds__(1024) void scan_kernel() {
    __shared__ int wsum[32];
    __shared__ bool is_last;
    int tid = threadIdx.x, lane = tid & 31, w = tid >> 5;
    int i = blockIdx.x * 1024 + tid;
    int v = (i < M_CNT) ? g_cnt[i] : 0;
    int incl = v;
    #pragma unroll
    for (int o = 1; o < 32; o <<= 1) {
        int t = __shfl_up_sync(0xffffffffu, incl, o);
        if (lane >= o) incl += t;
    }
    if (lane == 31) wsum[w] = incl;
    __syncthreads();
    if (w == 0) {
        int s0 = wsum[lane];
        int si = s0;
        #pragma unroll
        for (int o = 1; o < 32; o <<= 1) {
            int t = __shfl_up_sync(0xffffffffu, si, o);
            if (lane >= o) si += t;
        }
        wsum[lane] = si - s0;
    }
    __syncthreads();
    int excl = wsum[w] + incl - v;
    if (i <= M_CNT) g_off[i] = excl;
    if (tid == 1023) g_bsum[blockIdx.x] = wsum[31] + incl;

    // last block scans the 40 block totals (one warp, no extra launch)
    __threadfence();
    __syncthreads();
    if (tid == 0) {
        int t = atomicAdd(&g_scan_done, 1);
        is_last = (t == SCAN_BLKS - 1);
    }
    __syncthreads();
    if (is_last && tid < 32) {
        int v0 = g_bsum[lane];                       // totals 0..31
        int v1 = (lane < 8) ? g_bsum[32 + lane] : 0; // totals 32..39
        int i0 = v0;
        #pragma unroll
        for (int o = 1; o < 32; o <<= 1) {
            int t = __shfl_up_sync(0xffffffffu, i0, o);
            if (lane >= o) i0 += t;
        }
        int tot0 = __shfl_sync(0xffffffffu, i0, 31);
        int i1 = v1;
        #pragma unroll
        for (int o = 1; o < 8; o <<= 1) {
            int t = __shfl_up_sync(0xffffffffu, i1, o);
            if (lane >= o) i1 += t;
        }
        int t8 = __shfl_sync(0xffffffffu, i1, 7);
        g_bbase[lane] = i0 - v0;
        if (lane < 8)  g_bbase[32 + lane] = tot0 + (i1 - v1);
        if (lane == 8) g_bbase[40] = tot0 + t8;
    }
}

__device__ __forceinline__ int final_off(int i) {
    return g_off[i] + g_bbase[i >> 10];
}

// ---------------- fill CSR ----------------
__global__ void fill_kernel(const int* __restrict__ perms,
                            const int* __restrict__ edge_index,
                            const int* __restrict__ edge_type) {
    int i = blockIdx.x * blockDim.x + threadIdx.x;
    if (i >= NS * PP) return;
    int s = i / PP;
    int e = perms[i];
    int src = edge_index[e];
    int dst = edge_index[EE + e];
    int et  = edge_type[e];
    int idx = dst * NS + s;
    int pos = atomicAdd(&g_cur[idx], 1);
    g_csr[final_off(idx) + pos] = src | (et << 16);
}

// ---------------- tokenize kernel: one block per node (high occupancy) ----------------
__global__ __launch_bounds__(128) void tok_kernel(
    const float* __restrict__ x,
    const float* __restrict__ rel)
{
    int n = blockIdx.x;
    int d = threadIdx.x;
    float* trow = g_tok + n * (S * D);
    trow[d] = x[n * D + d];                       // token 0 = x[n]
    #pragma unroll
    for (int s = 0; s < NS; s++) {
        int idx = n * NS + s;
        int b = final_off(idx), e2 = final_off(idx + 1);
        float a0 = 0.f, a1 = 0.f, a2 = 0.f, a3 = 0.f;
        int t = b;
        for (; t + 4 <= e2; t += 4) {
            int p0 = g_csr[t], p1 = g_csr[t + 1];
            int p2 = g_csr[t + 2], p3 = g_csr[t + 3];
            a0 += x[(p0 & 0xFFFF) * D + d] + rel[(p0 >> 16) * D + d];
            a1 += x[(p1 & 0xFFFF) * D + d] + rel[(p1 >> 16) * D + d];
            a2 += x[(p2 & 0xFFFF) * D + d] + rel[(p2 >> 16) * D + d];
            a3 += x[(p3 & 0xFFFF) * D + d] + rel[(p3 >> 16) * D + d];
        }
        for (; t < e2; t++) {
            int pk = g_csr[t];
            a0 += x[(pk & 0xFFFF) * D + d] + rel[(pk >> 16) * D + d];
        }
        float acc = (a0 + a1) + (a2 + a3);
        int cnt = e2 - b;
        trow[(1 + s) * D + d] = acc / (float)(cnt > 1 ? cnt : 1);
    }
}

// ---------------- mamba kernel: NPB nodes per block, f32x2-packed math ----------------
__global__ __launch_bounds__(128) void mamba_kernel(
    const float* __restrict__ W_B,
    const float* __restrict__ W_C,
    const float* __restrict__ W_delta,
    const float* __restrict__ b_delta,
    const float* __restrict__ W_g,
    const float* __restrict__ b_g,
    const float* __restrict__ W_out,
    const float* __restrict__ b_out,
    const float* __restrict__ ln_g,
    const float* __restrict__ ln_b,
    float* __restrict__ out)
{
    int n0 = blockIdx.x * NPB;
    int d = threadIdx.x;                  // channel, 0..127
    int lane = d & 31, warp = d >> 5;

    __shared__ __align__(16) float tok[NPB][S][D];     // 10 KB
    __shared__ __align__(16) float BC[NPB][2][S][KK];  // 2.5 KB
    __shared__ float part[NPB][2][KK][4][S];           // 10 KB
    __shared__ __align__(16) float scn[NPB][D];        // 2 KB
    __shared__ float rs1[NPB][4], rs2[NPB][4];

    // ---- stream tokens from gmem (coalesced float4) ----
    {
        const float4* src = (const float4*)(g_tok + n0 * (S * D));
        float4* dst = (float4*)&tok[0][0][0];
        #pragma unroll
        for (int i = d; i < NPB * S * D / 4; i += 128) dst[i] = src[i];
    }
    __syncthreads();

    float xv[NPB];
    #pragma unroll
    for (int m = 0; m < NPB; m++) xv[m] = tok[m][0][d];

    // ---- delta GEMV: f32x2-packed over j-pairs ----
    float dl[NPB][S];
    {
        float bd = b_delta[d];
        u64 bd2; PACK2(bd2, bd, 0.f);
        u64 acc2[NPB][S];
        #pragma unroll
        for (int m = 0; m < NPB; m++)
            #pragma unroll
            for (int s = 0; s < S; s++) acc2[m][s] = bd2;
        #pragma unroll 2
        for (int j = 0; j < D; j += 4) {
            float w0 = W_delta[(j + 0) * D + d];
            float w1 = W_delta[(j + 1) * D + d];
            float w2 = W_delta[(j + 2) * D + d];
            float w3 = W_delta[(j + 3) * D + d];
            u64 wA, wB; PACK2(wA, w0, w1); PACK2(wB, w2, w3);
            #pragma unroll
            for (int m = 0; m < NPB; m++) {
                #pragma unroll
                for (int s = 0; s < S; s++) {
                    ulonglong2 t2 = *(const ulonglong2*)&tok[m][s][j];
                    FMA2(acc2[m][s], t2.x, wA, acc2[m][s]);
                    FMA2(acc2[m][s], t2.y, wB, acc2[m][s]);
                }
            }
        }
        #pragma unroll
        for (int m = 0; m < NPB; m++)
            #pragma unroll
            for (int s = 0; s < S; s++) {
                float lo, hi; UNPACK2(lo, hi, acc2[m][s]);
                dl[m][s] = softplus_f(lo + hi);
            }
    }

    // ---- B/C GEMVs: thread -> (mat, k, q); interleaved j = 4*i+q ----
    {
        int mat = d >> 6;
        int k   = (d >> 2) & 15;
        int q   = d & 3;
        const float* W = mat ? W_C : W_B;
        #pragma unroll
        for (int m = 0; m < NPB; m++) {
            float acc[S] = {0.f, 0.f, 0.f, 0.f, 0.f};
            #pragma unroll 8
            for (int i = 0; i < 32; i++) {
                int j = 4 * i + q;
                float w = W[j * KK + k];
                #pragma unroll
                for (int s = 0; s < S; s++) acc[s] += tok[m][s][j] * w;
            }
            #pragma unroll
            for (int s = 0; s < S; s++) part[m][mat][k][q][s] = acc[s];
        }
    }
    __syncthreads();
    if (d < 2 * KK) {
        int mat = d >> 4, k = d & 15;
        #pragma unroll
        for (int m = 0; m < NPB; m++)
            #pragma unroll
            for (int s = 0; s < S; s++)
                BC[m][mat][s][k] = part[m][mat][k][0][s] + part[m][mat][k][1][s]
                                 + part[m][mat][k][2][s] + part[m][mat][k][3][s];
    }
    __syncthreads();

    // ---- bidirectional selective scan: f32x2-packed over k-pairs ----
    // A2[kp] = {A[2kp], A[2kp+1]} * log2(e), so exp(dls*A) == ex2(dls*A2)
    u64 A2[KK / 2];
    {
        const float L2E = 1.44269504f;
        const float4* ar = (const float4*)(g_Acont + d * KK);
        #pragma unroll
        for (int k4 = 0; k4 < 4; k4++) {
            float4 a4 = ar[k4];
            PACK2(A2[2 * k4 + 0], a4.x * L2E, a4.y * L2E);
            PACK2(A2[2 * k4 + 1], a4.z * L2E, a4.w * L2E);
        }
    }
    #pragma unroll
    for (int m = 0; m < NPB; m++) {
        u64 dls2[S], dx2[S];
        #pragma unroll
        for (int s = 0; s < S; s++) {
            float dls = dl[m][s];
            float dx  = dls * tok[m][s][d];
            PACK2(dls2[s], dls, dls);
            PACK2(dx2[s], dx, dx);
        }
        u64 ysum2 = 0ull;   // {0.f, 0.f}
        {   // forward
            u64 st2[KK / 2];
            #pragma unroll
            for (int kp = 0; kp < KK / 2; kp++) st2[kp] = 0ull;
            #pragma unroll
            for (int s = 0; s < S; s++) {
                #pragma unroll
                for (int kp = 0; kp < KK / 2; kp++) {
                    u64 arg2; MUL2(arg2, dls2[s], A2[kp]);
                    float e0, e1; UNPACK2(e0, e1, arg2);
                    e0 = ex2f(e0); e1 = ex2f(e1);
                    u64 a2; PACK2(a2, e0, e1);
                    u64 b2 = *(const u64*)&BC[m][0][s][2 * kp];
                    u64 c2 = *(const u64*)&BC[m][1][s][2 * kp];
                    u64 t2; MUL2(t2, dx2[s], b2);
                    FMA2(st2[kp], a2, st2[kp], t2);
                    FMA2(ysum2, st2[kp], c2, ysum2);
                }
            }
        }
        {   // backward
            u64 st2[KK / 2];
            #pragma unroll
            for (int kp = 0; kp < KK / 2; kp++) st2[kp] = 0ull;
            #pragma unroll
            for (int s = S - 1; s >= 0; s--) {
                #pragma unroll
                for (int kp = 0; kp < KK / 2; kp++) {
                    u64 arg2; MUL2(arg2, dls2[s], A2[kp]);
                    float e0, e1; UNPACK2(e0, e1, arg2);
                    e0 = ex2f(e0); e1 = ex2f(e1);
                    u64 a2; PACK2(a2, e0, e1);
                    u64 b2 = *(const u64*)&BC[m][0][s][2 * kp];
                    u64 c2 = *(const u64*)&BC[m][1][s][2 * kp];
                    u64 t2; MUL2(t2, dx2[s], b2);
                    FMA2(st2[kp], a2, st2[kp], t2);
                    FMA2(ysum2, st2[kp], c2, ysum2);
                }
            }
        }
        float ylo, yhi; UNPACK2(ylo, yhi, ysum2);
        scn[m][d] = (ylo + yhi) * (1.f / (float)S);
    }
    __syncthreads();

    // ---- gate & out GEMVs: f32x2-packed over j-pairs ----
    float ga[NPB], oa[NPB];
    {
        float bg = b_g[d], bo = b_out[d];
        u64 bg2, bo2; PACK2(bg2, bg, 0.f); PACK2(bo2, bo, 0.f);
        u64 ga2[NPB], oa2[NPB];
        #pragma unroll
        for (int m = 0; m < NPB; m++) { ga2[m] = bg2; oa2[m] = bo2; }
        #pragma unroll 2
        for (int j = 0; j < D; j += 4) {
            float g0 = W_g[(j + 0) * D + d];
            float g1 = W_g[(j + 1) * D + d];
            float g2 = W_g[(j + 2) * D + d];
            float g3 = W_g[(j + 3) * D + d];
            float o0 = W_out[(j + 0) * D + d];
            float o1 = W_out[(j + 1) * D + d];
            float o2 = W_out[(j + 2) * D + d];
            float o3 = W_out[(j + 3) * D + d];
            u64 gA, gB, oA, oB;
            PACK2(gA, g0, g1); PACK2(gB, g2, g3);
            PACK2(oA, o0, o1); PACK2(oB, o2, o3);
            #pragma unroll
            for (int m = 0; m < NPB; m++) {
                ulonglong2 x2 = *(const ulonglong2*)&tok[m][0][j];
                ulonglong2 s2 = *(const ulonglong2*)&scn[m][j];
                FMA2(ga2[m], x2.x, gA, ga2[m]);
                FMA2(ga2[m], x2.y, gB, ga2[m]);
                FMA2(oa2[m], s2.x, oA, oa2[m]);
                FMA2(oa2[m], s2.y, oB, oa2[m]);
            }
        }
        #pragma unroll
        for (int m = 0; m < NPB; m++) {
            float lo, hi;
            UNPACK2(lo, hi, ga2[m]); ga[m] = lo + hi;
            UNPACK2(lo, hi, oa2[m]); oa[m] = lo + hi;
        }
    }

    // ---- residual + layernorm per node ----
    float res[NPB];
    #pragma unroll
    for (int m = 0; m < NPB; m++) {
        float gate = ga[m] / (1.f + __expf(-ga[m]));   // silu
        res[m] = xv[m] + gate * oa[m];
        float s1 = res[m], s2 = res[m] * res[m];
        #pragma unroll
        for (int o = 16; o > 0; o >>= 1) {
            s1 += __shfl_xor_sync(0xffffffffu, s1, o);
            s2 += __shfl_xor_sync(0xffffffffu, s2, o);
        }
        if (lane == 0) { rs1[m][warp] = s1; rs2[m][warp] = s2; }
    }
    __syncthreads();
    float lg = ln_g[d], lb = ln_b[d];
    #pragma unroll
    for (int m = 0; m < NPB; m++) {
        float t1 = rs1[m][0] + rs1[m][1] + rs1[m][2] + rs1[m][3];
        float t2 = rs2[m][0] + rs2[m][1] + rs2[m][2] + rs2[m][3];
        float mu  = t1 * (1.f / (float)D);
        float var = t2 * (1.f / (float)D) - mu * mu;
        float inv = rsqrtf(var + LN_EPS);
        out[(n0 + m) * D + d] = (res[m] - mu) * inv * lg + lb;
    }
}

// ---------------- launch ----------------
extern "C" void kernel_launch(void* const* d_in, const int* in_sizes, int n_in,
                              void* d_out, int out_size) {
    const float* x         = (const float*)d_in[0];
    const int*   edge_index= (const int*)  d_in[1];
    const int*   edge_type = (const int*)  d_in[2];
    const int*   perms     = (const int*)  d_in[3];
    const float* rel       = (const float*)d_in[4];
    const float* logA      = (const float*)d_in[5];
    const float* W_B       = (const float*)d_in[6];
    const float* W_C       = (const float*)d_in[7];
    const float* W_delta   = (const float*)d_in[8];
    const float* b_delta   = (const float*)d_in[9];
    const float* W_g       = (const float*)d_in[10];
    const float* b_g       = (const float*)d_in[11];
    const float* W_out     = (const float*)d_in[12];
    const float* b_out     = (const float*)d_in[13];
    const float* ln_g      = (const float*)d_in[14];
    const float* ln_b      = (const float*)d_in[15];
    float* out = (float*)d_out;

    prep_zero_kernel<<<(M_CNT + 255) / 256, 256>>>(logA);
    count_kernel<<<(NS * PP + 255) / 256, 256>>>(perms, edge_index);
    scan_kernel<<<SCAN_BLKS, 1024>>>();
    fill_kernel<<<(NS * PP + 255) / 256, 256>>>(perms, edge_index, edge_type);
    tok_kernel<<<NN, 128>>>(x, rel);
    mamba_kernel<<<NN / NPB, 128>>>(W_B, W_C, W_delta, b_delta,
                                    W_g, b_g, W_out, b_out, ln_g, ln_b, out);
}